// round 2
// baseline (speedup 1.0000x reference)
#include <cuda_runtime.h>
#include <math.h>

#define NN   30000
#define EE   480000
#define NFD  128
#define EFD  64
#define HID  256
#define LL   4
#define NH   8
#define DD   32

#define OFF_H 0
#define OFF_G (NN*HID)
#define OFF_C (NN*HID + HID)
#define OFF_S (NN*HID + HID + NN)

// ---------------- static device scratch (no allocations allowed) ----------------
__device__ float d_h [NN*HID];
__device__ float d_Q [NN*HID];
__device__ float d_Kt[NN*HID];
__device__ float d_Vt[NN*HID];
__device__ float d_SK[NN*HID];
__device__ float d_AGG[NN*HID];
__device__ float d_KE[(size_t)EE*HID];          // 491 MB
__device__ float d_Wcomb[LL*EFD*HID];
__device__ float d_bcomb[LL*HID];
__device__ float d_T1[NN*(HID/2)];
__device__ int   d_counts[NN];
__device__ int   d_cursor[NN];
__device__ int   d_rowptr[NN+1];
__device__ int   d_perm[EE];

// ---------------- helpers ----------------
__device__ __forceinline__ float warp_sum(float v) {
    v += __shfl_xor_sync(0xffffffffu, v, 16);
    v += __shfl_xor_sync(0xffffffffu, v, 8);
    v += __shfl_xor_sync(0xffffffffu, v, 4);
    v += __shfl_xor_sync(0xffffffffu, v, 2);
    v += __shfl_xor_sync(0xffffffffu, v, 1);
    return v;
}

// ---------------- generic fp32 GEMM: C[M,N] = A[M,K] @ B[K,N] (+bias) (+relu) ----------------
// BM=128, BN=64, BK=16, 256 threads, 8x4 per thread. N, K multiples of 16; M guarded.
__global__ __launch_bounds__(256) void sgemm(
    const float* __restrict__ A, const float* __restrict__ B,
    const float* __restrict__ bias, float* __restrict__ C,
    int M, int N, int K, int act)
{
    __shared__ float As[16][128];
    __shared__ float Bs[16][64];
    const int tid = threadIdx.x;
    const int tx = tid & 15;        // 0..15 -> col group
    const int ty = tid >> 4;        // 0..15 -> row group
    const int rowBase = blockIdx.y * 128;
    const int colBase = blockIdx.x * 64;

    float acc[8][4];
#pragma unroll
    for (int i = 0; i < 8; i++)
#pragma unroll
        for (int j = 0; j < 4; j++) acc[i][j] = 0.f;

    for (int k0 = 0; k0 < K; k0 += 16) {
        // A tile: 128 rows x 16 k  = 512 float4, 2 per thread
#pragma unroll
        for (int it = 0; it < 2; it++) {
            int li = tid * 2 + it;
            int r  = li >> 2;
            int k4 = li & 3;
            int row = rowBase + r;
            float4 a = make_float4(0.f, 0.f, 0.f, 0.f);
            if (row < M) a = *(const float4*)(A + (size_t)row * K + k0 + k4 * 4);
            As[k4*4+0][r] = a.x; As[k4*4+1][r] = a.y;
            As[k4*4+2][r] = a.z; As[k4*4+3][r] = a.w;
        }
        // B tile: 16 k x 64 cols = 256 float4, 1 per thread
        {
            int r  = tid >> 4;
            int c4 = tid & 15;
            float4 b = *(const float4*)(B + (size_t)(k0 + r) * N + colBase + c4 * 4);
            *(float4*)&Bs[r][c4 * 4] = b;
        }
        __syncthreads();
#pragma unroll
        for (int kk = 0; kk < 16; kk++) {
            float4 b4 = *(float4*)&Bs[kk][tx * 4];
            float4 a0 = *(float4*)&As[kk][ty * 8];
            float4 a1 = *(float4*)&As[kk][ty * 8 + 4];
            float a[8] = {a0.x, a0.y, a0.z, a0.w, a1.x, a1.y, a1.z, a1.w};
#pragma unroll
            for (int i = 0; i < 8; i++) {
                acc[i][0] += a[i] * b4.x;
                acc[i][1] += a[i] * b4.y;
                acc[i][2] += a[i] * b4.z;
                acc[i][3] += a[i] * b4.w;
            }
        }
        __syncthreads();
    }
    // epilogue
#pragma unroll
    for (int i = 0; i < 8; i++) {
        int row = rowBase + ty * 8 + i;
        if (row >= M) continue;
        int col = colBase + tx * 4;
        float4 v = make_float4(acc[i][0], acc[i][1], acc[i][2], acc[i][3]);
        if (bias) {
            float4 bb = *(const float4*)(bias + col);
            v.x += bb.x; v.y += bb.y; v.z += bb.z; v.w += bb.w;
        }
        if (act == 1) {
            v.x = fmaxf(v.x, 0.f); v.y = fmaxf(v.y, 0.f);
            v.z = fmaxf(v.z, 0.f); v.w = fmaxf(v.w, 0.f);
        }
        *(float4*)(C + (size_t)row * N + col) = v;
    }
}

// bcomb[l] = enc_be @ We[l]   (vector [256] x [256,256])
__global__ void vecmat_kernel(const float* __restrict__ x, const float* __restrict__ W,
                              float* __restrict__ y)
{
    int l = blockIdx.x;
    int j = threadIdx.x;
    const float* Wl = W + (size_t)l * HID * HID;
    float s = 0.f;
    for (int k = 0; k < HID; k++) s += x[k] * Wl[k * HID + j];
    y[l * HID + j] = s;
}

// ---------------- CSR build ----------------
__global__ void zero_int_kernel(int* p, int n) {
    int i = blockIdx.x * 256 + threadIdx.x;
    if (i < n) p[i] = 0;
}
__global__ void hist_kernel(const int* __restrict__ dst, int* __restrict__ counts) {
    int e = blockIdx.x * 256 + threadIdx.x;
    if (e < EE) atomicAdd(&counts[dst[e]], 1);
}
__global__ void scan_kernel(const int* __restrict__ counts, int* __restrict__ rowptr, int n) {
    __shared__ int sh[1024];
    __shared__ int carry;
    if (threadIdx.x == 0) carry = 0;
    __syncthreads();
    for (int base = 0; base < n; base += 1024) {
        int i = base + threadIdx.x;
        int v = (i < n) ? counts[i] : 0;
        sh[threadIdx.x] = v;
        __syncthreads();
        for (int off = 1; off < 1024; off <<= 1) {
            int t = (threadIdx.x >= off) ? sh[threadIdx.x - off] : 0;
            __syncthreads();
            sh[threadIdx.x] += t;
            __syncthreads();
        }
        if (i < n) rowptr[i + 1] = carry + sh[threadIdx.x];
        __syncthreads();
        if (threadIdx.x == 1023) carry += sh[1023];
        __syncthreads();
    }
    if (threadIdx.x == 0) rowptr[0] = 0;
}
__global__ void scatter_kernel(const int* __restrict__ dst, const int* __restrict__ rowptr,
                               int* __restrict__ cursor, int* __restrict__ perm) {
    int e = blockIdx.x * 256 + threadIdx.x;
    if (e >= EE) return;
    int d = dst[e];
    int pos = rowptr[d] + atomicAdd(&cursor[d], 1);
    perm[pos] = e;
}

// ---------------- attention: one block per dst node, one warp per head ----------------
__global__ __launch_bounds__(256) void attn_kernel(
    const float* __restrict__ Q, const float* __restrict__ K, const float* __restrict__ V,
    const float* __restrict__ KE, const int* __restrict__ src,
    const int* __restrict__ perm, const int* __restrict__ rowptr,
    float* __restrict__ AGG)
{
    const int n    = blockIdx.x;
    const int warp = threadIdx.x >> 5;
    const int lane = threadIdx.x & 31;
    const int col  = warp * DD + lane;
    const int beg = rowptr[n], end = rowptr[n + 1];
    const float q = Q[(size_t)n * HID + col];
    const float inv_sqrt_d = 0.17677669529663687f; // 1/sqrt(32)

    float m = -3.0e38f, s = 0.f, acc = 0.f;
    __shared__ int sh_e[128], sh_s[128];

    for (int base = beg; base < end; base += 128) {
        int cnt = min(128, end - base);
        __syncthreads();
        for (int t = threadIdx.x; t < cnt; t += blockDim.x) {
            int e = perm[base + t];
            sh_e[t] = e;
            sh_s[t] = src[e];
        }
        __syncthreads();
        for (int j = 0; j < cnt; j++) {
            int e  = sh_e[j];
            int sn = sh_s[j];
            float ke = KE[(size_t)e * HID + col];
            float kk = K[(size_t)sn * HID + col] + ke;
            float vv = V[(size_t)sn * HID + col] + ke;
            float sc = warp_sum(q * kk) * inv_sqrt_d;
            float mn = fmaxf(m, sc);
            float scale = __expf(m - mn);
            float p     = __expf(sc - mn);
            s   = s   * scale + p;
            acc = acc * scale + p * vv;
            m = mn;
        }
    }
    AGG[(size_t)n * HID + col] = acc / (s + 1e-16f);
}

// ---------------- residual + shared LayerNorm (in place on h), warp per row ----------------
__global__ __launch_bounds__(256) void resid_ln_kernel(
    float* __restrict__ h, const float* __restrict__ AGG, const float* __restrict__ SK,
    const float* __restrict__ g, const float* __restrict__ b)
{
    int row  = blockIdx.x * 8 + (threadIdx.x >> 5);
    if (row >= NN) return;
    int lane = threadIdx.x & 31;
    float v[8];
    float s = 0.f;
#pragma unroll
    for (int i = 0; i < 8; i++) {
        int c = lane + 32 * i;
        size_t idx = (size_t)row * HID + c;
        v[i] = h[idx] + AGG[idx] + SK[idx];
        s += v[i];
    }
    float mean = warp_sum(s) * (1.0f / HID);
    float var = 0.f;
#pragma unroll
    for (int i = 0; i < 8; i++) { float d = v[i] - mean; var += d * d; }
    var = warp_sum(var) * (1.0f / HID);
    float r = rsqrtf(var + 1e-5f);
#pragma unroll
    for (int i = 0; i < 8; i++) {
        int c = lane + 32 * i;
        h[(size_t)row * HID + c] = (v[i] - mean) * r * g[c] + b[c];
    }
}

// ---------------- output assembly ----------------
__global__ void copy_h_kernel(const float* __restrict__ h, float* __restrict__ out) {
    size_t i = (size_t)blockIdx.x * 256 + threadIdx.x;
    size_t total = (size_t)NN * HID;
    size_t stride = (size_t)gridDim.x * 256;
    for (; i < total; i += stride) out[OFF_H + i] = h[i];
}
__global__ void zero_g_kernel(float* __restrict__ out) {
    out[OFF_G + threadIdx.x] = 0.f;
}
__global__ void mean_pool_kernel(const float* __restrict__ h, float* __restrict__ out) {
    int per = (NN + gridDim.x - 1) / gridDim.x;
    int r0 = blockIdx.x * per, r1 = min(NN, r0 + per);
    float s = 0.f;
    for (int r = r0; r < r1; r++) s += h[(size_t)r * HID + threadIdx.x];
    atomicAdd(&out[OFF_G + threadIdx.x], s * (1.0f / NN));
}
// contagion: dot(T1_row[128], W2) + b2 -> sigmoid. Warp per node.
__global__ __launch_bounds__(256) void contagion_kernel(
    const float* __restrict__ T1, const float* __restrict__ W2,
    const float* __restrict__ b2, float* __restrict__ out)
{
    int n = blockIdx.x * 8 + (threadIdx.x >> 5);
    if (n >= NN) return;
    int lane = threadIdx.x & 31;
    float s = 0.f;
#pragma unroll
    for (int i = 0; i < 4; i++) {
        int c = lane + 32 * i;
        s += T1[(size_t)n * 128 + c] * W2[c];
    }
    s = warp_sum(s);
    if (lane == 0) out[OFF_C + n] = 1.f / (1.f + expf(-(s + b2[0])));
}
__global__ void systemic_kernel(const float* __restrict__ W1, const float* __restrict__ b1,
                                const float* __restrict__ W2, const float* __restrict__ b2,
                                float* __restrict__ out)
{
    __shared__ float sh[128];
    int j = threadIdx.x;  // 128 threads
    const float* g = out + OFF_G;
    float t = b1[j];
    for (int k = 0; k < HID; k++) t += g[k] * W1[k * 128 + j];
    sh[j] = fmaxf(t, 0.f) * W2[j];
    __syncthreads();
    for (int off = 64; off > 0; off >>= 1) {
        if (j < off) sh[j] += sh[j + off];
        __syncthreads();
    }
    if (j == 0) out[OFF_S] = 1.f / (1.f + expf(-(sh[0] + b2[0])));
}

// ---------------- host ----------------
static inline void* sym(const void* s) { void* p = nullptr; cudaGetSymbolAddress(&p, s); return p; }

extern "C" void kernel_launch(void* const* d_in, const int* in_sizes, int n_in,
                              void* d_out, int out_size)
{
    const float* x         = (const float*)d_in[0];
    const float* edge_attr = (const float*)d_in[1];
    const int*   edge_index= (const int*)  d_in[2];
    const float* enc_Wn = (const float*)d_in[3];
    const float* enc_bn = (const float*)d_in[4];
    const float* enc_We = (const float*)d_in[5];
    const float* enc_be = (const float*)d_in[6];
    const float* Wq = (const float*)d_in[7];  const float* bq = (const float*)d_in[8];
    const float* Wk = (const float*)d_in[9];  const float* bk = (const float*)d_in[10];
    const float* Wv = (const float*)d_in[11]; const float* bv = (const float*)d_in[12];
    const float* We = (const float*)d_in[13];
    const float* Wsk= (const float*)d_in[14]; const float* bsk= (const float*)d_in[15];
    const float* ln_g = (const float*)d_in[16];
    const float* ln_b = (const float*)d_in[17];
    const float* cp_W1 = (const float*)d_in[18]; const float* cp_b1 = (const float*)d_in[19];
    const float* cp_W2 = (const float*)d_in[20]; const float* cp_b2 = (const float*)d_in[21];
    const float* sp_W1 = (const float*)d_in[22]; const float* sp_b1 = (const float*)d_in[23];
    const float* sp_W2 = (const float*)d_in[24]; const float* sp_b2 = (const float*)d_in[25];
    float* out = (float*)d_out;

    float* h    = (float*)sym(d_h);
    float* Qb   = (float*)sym(d_Q);
    float* Ktb  = (float*)sym(d_Kt);
    float* Vtb  = (float*)sym(d_Vt);
    float* SKb  = (float*)sym(d_SK);
    float* AGGb = (float*)sym(d_AGG);
    float* KEb  = (float*)sym(d_KE);
    float* Wcomb= (float*)sym(d_Wcomb);
    float* bcomb= (float*)sym(d_bcomb);
    float* T1   = (float*)sym(d_T1);
    int* counts = (int*)sym(d_counts);
    int* cursor = (int*)sym(d_cursor);
    int* rowptr = (int*)sym(d_rowptr);
    int* perm   = (int*)sym(d_perm);

    const int* src = edge_index;
    const int* dst = edge_index + EE;

    // 1) node encoder: h = x @ enc_Wn + enc_bn
    {
        dim3 g(HID / 64, (NN + 127) / 128);
        sgemm<<<g, 256>>>(x, enc_Wn, enc_bn, h, NN, HID, NFD, 0);
    }
    // 2) combined edge weights: Wcomb[l] = enc_We @ We[l] ; bcomb[l] = enc_be @ We[l]
    for (int l = 0; l < LL; l++) {
        dim3 g(HID / 64, 1);
        sgemm<<<g, 256>>>(enc_We, We + (size_t)l * HID * HID, nullptr,
                          Wcomb + (size_t)l * EFD * HID, EFD, HID, HID, 0);
    }
    vecmat_kernel<<<LL, HID>>>(enc_be, We, bcomb);

    // 3) CSR build (by dst)
    zero_int_kernel<<<(NN + 255) / 256, 256>>>(counts, NN);
    zero_int_kernel<<<(NN + 255) / 256, 256>>>(cursor, NN);
    hist_kernel<<<(EE + 255) / 256, 256>>>(dst, counts);
    scan_kernel<<<1, 1024>>>(counts, rowptr, NN);
    scatter_kernel<<<(EE + 255) / 256, 256>>>(dst, rowptr, cursor, perm);

    // 4) layers
    for (int l = 0; l < LL; l++) {
        size_t wo = (size_t)l * HID * HID;
        size_t bo = (size_t)l * HID;
        {   // KE = edge_attr @ Wcomb[l] + bcomb[l]
            dim3 g(HID / 64, (EE + 127) / 128);
            sgemm<<<g, 256>>>(edge_attr, Wcomb + (size_t)l * EFD * HID,
                              bcomb + bo, KEb, EE, HID, EFD, 0);
        }
        dim3 gn(HID / 64, (NN + 127) / 128);
        sgemm<<<gn, 256>>>(h, Wq + wo, bq + bo, Qb,  NN, HID, HID, 0);
        sgemm<<<gn, 256>>>(h, Wk + wo, bk + bo, Ktb, NN, HID, HID, 0);
        sgemm<<<gn, 256>>>(h, Wv + wo, bv + bo, Vtb, NN, HID, HID, 0);
        sgemm<<<gn, 256>>>(h, Wsk + wo, bsk + bo, SKb, NN, HID, HID, 0);

        attn_kernel<<<NN, 256>>>(Qb, Ktb, Vtb, KEb, src, perm, rowptr, AGGb);
        resid_ln_kernel<<<(NN + 7) / 8, 256>>>(h, AGGb, SKb, ln_g, ln_b);
    }

    // 5) outputs
    copy_h_kernel<<<1024, 256>>>(h, out);
    zero_g_kernel<<<1, HID>>>(out);
    mean_pool_kernel<<<128, HID>>>(h, out);
    {
        dim3 g(128 / 64, (NN + 127) / 128);
        sgemm<<<g, 256>>>(h, cp_W1, cp_b1, T1, NN, 128, HID, 1);
    }
    contagion_kernel<<<(NN + 7) / 8, 256>>>(T1, cp_W2, cp_b2, out);
    systemic_kernel<<<1, 128>>>(sp_W1, sp_b1, sp_W2, sp_b2, out);
}